// round 5
// baseline (speedup 1.0000x reference)
#include <cuda_runtime.h>

#define NN 50000
#define EE 800000
#define FF 128
#define HH 64
#define CC 40

// ---------------- scratch (device globals: no allocation allowed) ----------
__device__ __align__(16) float g_y1[NN * HH];    // x @ Wl1
__device__ __align__(16) float g_z1[NN * HH];    // x @ Wr1
__device__ __align__(16) float g_xa[NN * HH];    // x @ Wlin[0:128]
__device__ __align__(16) float g_agg1[NN * HH];  // segment-sum of y1[src] by dst
__device__ __align__(16) float g_hid[NN * HH];   // relu(l2norm(agg1/cnt + bl1 + z1))
__device__ __align__(16) float g_h[NN * HH];     // relu(xa + hid @ Wlin[128:] + blin)
__device__ __align__(16) float g_y2[NN * CC];    // h @ Wl2
__device__ __align__(16) float g_z2[NN * CC];    // h @ Wr2
__device__ __align__(16) float g_agg2[NN * CC];  // segment-sum of y2[src] by dst
__device__ int g_cnt[NN];                        // in-degree
__device__ int g_src[EE];                        // normalized int32 src indices
__device__ int g_dst[EE];                        // normalized int32 dst indices
__device__ int g_is64;                           // 1 if edge_index is int64

__device__ __forceinline__ void red_add_v4(float* p, float4 v) {
    asm volatile("red.global.add.v4.f32 [%0], {%1, %2, %3, %4};"
                 :: "l"(p), "f"(v.x), "f"(v.y), "f"(v.z), "f"(v.w)
                 : "memory");
}

// ---------------- K-1: detect index dtype (reads ONLY first 1.6M words) ----
// If int64: words at odd positions in [0, 2*EE) are high words of src -> all 0.
// If int32: they are random node indices; 4096 samples all-zero is impossible.
__global__ void k_detect(const unsigned* __restrict__ ei_w) {
    __shared__ int s_nz;
    if (threadIdx.x == 0) s_nz = 0;
    __syncthreads();
    int nz = 0;
    // probe odd words spread across the first 2*EE 32-bit words (always in-bounds)
    for (int i = threadIdx.x; i < 4096; i += blockDim.x) {
        unsigned pos = 2u * (unsigned)((long long)i * (EE - 1) / 4095) + 1u;
        if (ei_w[pos] != 0u) nz = 1;
    }
    if (nz) atomicOr(&s_nz, 1);
    __syncthreads();
    if (threadIdx.x == 0) g_is64 = s_nz ? 0 : 1;
}

// ---------------- K0: zero accumulators + normalize edge indices -----------
__global__ void k_prep(const void* __restrict__ ei) {
    int i = blockIdx.x * blockDim.x + threadIdx.x;
    float4 z = make_float4(0.f, 0.f, 0.f, 0.f);
    if (i < NN * HH / 4) reinterpret_cast<float4*>(g_agg1)[i] = z;
    if (i < NN * CC / 4) reinterpret_cast<float4*>(g_agg2)[i] = z;
    if (i < NN) g_cnt[i] = 0;
    if (i < EE) {
        if (g_is64) {
            const long long* p = (const long long*)ei;
            g_src[i] = (int)p[i];
            g_dst[i] = (int)p[EE + i];
        } else {
            const int* p = (const int*)ei;
            g_src[i] = p[i];
            g_dst[i] = p[EE + i];
        }
    }
}

// ---------------- K1: fused 3x GEMM from x (K=128, 3 weights of 128x64) ----
__global__ __launch_bounds__(512) void k_gemm1(
    const float* __restrict__ x, const float* __restrict__ Wl1,
    const float* __restrict__ Wr1, const float* __restrict__ Wlin) {
    extern __shared__ float sm[];
    float* sW = sm;                 // 3 * 128 * 64
    float* sx = sm + 3 * FF * HH;   // 16 warps * 4 rows * 128
    int tid = threadIdx.x;
    for (int i = tid; i < FF * HH; i += blockDim.x) {
        sW[i]               = Wl1[i];
        sW[FF * HH + i]     = Wr1[i];
        sW[2 * FF * HH + i] = Wlin[i];  // rows 0..127 of Wlin
    }
    __syncthreads();
    int warp = tid >> 5, lane = tid & 31;
    int q = lane >> 3, li = lane & 7;
    float* sxw = sx + warp * (4 * FF);
    int nw = (gridDim.x * blockDim.x) >> 5;
    int gw = (blockIdx.x * blockDim.x + tid) >> 5;
    for (int grp = gw; grp < NN / 4; grp += nw) {
        int r0 = grp * 4;
        const float4* xv = reinterpret_cast<const float4*>(x + (size_t)r0 * FF);
        float4* sxv = reinterpret_cast<float4*>(sxw);
#pragma unroll
        for (int j = 0; j < 4; j++) sxv[lane + 32 * j] = xv[lane + 32 * j];
        __syncwarp();
        float acc[3][8];
#pragma unroll
        for (int w = 0; w < 3; w++)
#pragma unroll
            for (int j = 0; j < 8; j++) acc[w][j] = 0.f;
        const float* xr = sxw + q * FF;
#pragma unroll 8
        for (int k = 0; k < FF; k++) {
            float xk = xr[k];
#pragma unroll
            for (int w = 0; w < 3; w++) {
                const float4* wp = reinterpret_cast<const float4*>(
                    sW + w * FF * HH + k * HH + li * 8);
                float4 wa = wp[0], wb = wp[1];
                acc[w][0] = fmaf(xk, wa.x, acc[w][0]);
                acc[w][1] = fmaf(xk, wa.y, acc[w][1]);
                acc[w][2] = fmaf(xk, wa.z, acc[w][2]);
                acc[w][3] = fmaf(xk, wa.w, acc[w][3]);
                acc[w][4] = fmaf(xk, wb.x, acc[w][4]);
                acc[w][5] = fmaf(xk, wb.y, acc[w][5]);
                acc[w][6] = fmaf(xk, wb.z, acc[w][6]);
                acc[w][7] = fmaf(xk, wb.w, acc[w][7]);
            }
        }
        int row = r0 + q;
        float* outs[3] = {g_y1, g_z1, g_xa};
#pragma unroll
        for (int w = 0; w < 3; w++) {
            float4* op = reinterpret_cast<float4*>(outs[w] + (size_t)row * HH + li * 8);
            op[0] = make_float4(acc[w][0], acc[w][1], acc[w][2], acc[w][3]);
            op[1] = make_float4(acc[w][4], acc[w][5], acc[w][6], acc[w][7]);
        }
        __syncwarp();
    }
}

// ---------------- K2: conv1 scatter (64 floats/edge, vectorized L2 red) ----
__global__ void k_scatter1() {
    unsigned idx = blockIdx.x * blockDim.x + threadIdx.x;
    if (idx >= (unsigned)EE * 16u) return;
    unsigned e = idx >> 4, c = idx & 15;
    int s = g_src[e];
    int d = g_dst[e];
    float4 v = reinterpret_cast<const float4*>(g_y1 + (size_t)s * HH)[c];
    red_add_v4(g_agg1 + (size_t)d * HH + c * 4, v);
    if (c == 0) atomicAdd(&g_cnt[d], 1);
}

// ---------------- K3a: hidden = relu(l2norm(agg1/cnt + bl1 + z1)) ----------
__global__ void k_hidden(const float* __restrict__ bl1) {
    int gt = blockIdx.x * blockDim.x + threadIdx.x;
    int n = gt >> 5, lane = gt & 31;
    if (n >= NN) return;
    float invc = 1.f / (float)max(g_cnt[n], 1);
    size_t b = (size_t)n * HH;
    float v0 = g_agg1[b + lane] * invc + bl1[lane] + g_z1[b + lane];
    float v1 = g_agg1[b + 32 + lane] * invc + bl1[32 + lane] + g_z1[b + 32 + lane];
    float s = v0 * v0 + v1 * v1;
#pragma unroll
    for (int o = 16; o > 0; o >>= 1) s += __shfl_xor_sync(0xffffffffu, s, o);
    float inv = 1.f / fmaxf(sqrtf(s), 1e-12f);
    g_hid[b + lane]      = fmaxf(v0 * inv, 0.f);
    g_hid[b + 32 + lane] = fmaxf(v1 * inv, 0.f);
}

// ---------------- K3b: h = relu(xa + hid @ Wlin[128:] + blin) --------------
__global__ __launch_bounds__(512) void k_lin1(
    const float* __restrict__ Wlin, const float* __restrict__ blin) {
    __shared__ float sB[HH * HH];
    __shared__ float sb[HH];
    __shared__ float sx[16 * 4 * HH];
    int tid = threadIdx.x;
    for (int i = tid; i < HH * HH; i += blockDim.x) sB[i] = Wlin[FF * HH + i];
    if (tid < HH) sb[tid] = blin[tid];
    __syncthreads();
    int warp = tid >> 5, lane = tid & 31;
    int q = lane >> 3, li = lane & 7;
    float* sxw = sx + warp * (4 * HH);
    int nw = (gridDim.x * blockDim.x) >> 5;
    int gw = (blockIdx.x * blockDim.x + tid) >> 5;
    for (int grp = gw; grp < NN / 4; grp += nw) {
        int r0 = grp * 4;
        const float4* hv = reinterpret_cast<const float4*>(g_hid + (size_t)r0 * HH);
        float4* sxv = reinterpret_cast<float4*>(sxw);
        sxv[lane] = hv[lane];
        sxv[lane + 32] = hv[lane + 32];
        __syncwarp();
        float acc[8];
#pragma unroll
        for (int j = 0; j < 8; j++) acc[j] = 0.f;
        const float* xr = sxw + q * HH;
#pragma unroll 8
        for (int k = 0; k < HH; k++) {
            float xk = xr[k];
            const float4* wp = reinterpret_cast<const float4*>(sB + k * HH + li * 8);
            float4 wa = wp[0], wb = wp[1];
            acc[0] = fmaf(xk, wa.x, acc[0]);
            acc[1] = fmaf(xk, wa.y, acc[1]);
            acc[2] = fmaf(xk, wa.z, acc[2]);
            acc[3] = fmaf(xk, wa.w, acc[3]);
            acc[4] = fmaf(xk, wb.x, acc[4]);
            acc[5] = fmaf(xk, wb.y, acc[5]);
            acc[6] = fmaf(xk, wb.z, acc[6]);
            acc[7] = fmaf(xk, wb.w, acc[7]);
        }
        int row = r0 + q;
        const float* xap = g_xa + (size_t)row * HH + li * 8;
        float* hp = g_h + (size_t)row * HH + li * 8;
#pragma unroll
        for (int j = 0; j < 8; j++)
            hp[j] = fmaxf(acc[j] + xap[j] + sb[li * 8 + j], 0.f);
        __syncwarp();
    }
}

// ---------------- K3c: y2 = h @ Wl2, z2 = h @ Wr2 (K=64, 80 fused cols) ----
__global__ __launch_bounds__(512) void k_gemm2(
    const float* __restrict__ Wl2, const float* __restrict__ Wr2) {
    __shared__ float sW[HH * 80];  // [k][0:40)=Wl2, [k][40:80)=Wr2
    __shared__ float sx[16 * 4 * HH];
    int tid = threadIdx.x;
    for (int i = tid; i < HH * CC; i += blockDim.x) {
        int k = i / CC, c = i - k * CC;
        sW[k * 80 + c]      = Wl2[i];
        sW[k * 80 + 40 + c] = Wr2[i];
    }
    __syncthreads();
    int warp = tid >> 5, lane = tid & 31;
    int q = lane >> 3, li = lane & 7;
    int c0 = li * 10;
    float* sxw = sx + warp * (4 * HH);
    int nw = (gridDim.x * blockDim.x) >> 5;
    int gw = (blockIdx.x * blockDim.x + tid) >> 5;
    for (int grp = gw; grp < NN / 4; grp += nw) {
        int r0 = grp * 4;
        const float4* hv = reinterpret_cast<const float4*>(g_h + (size_t)r0 * HH);
        float4* sxv = reinterpret_cast<float4*>(sxw);
        sxv[lane] = hv[lane];
        sxv[lane + 32] = hv[lane + 32];
        __syncwarp();
        float acc[10];
#pragma unroll
        for (int j = 0; j < 10; j++) acc[j] = 0.f;
        const float* xr = sxw + q * HH;
#pragma unroll 8
        for (int k = 0; k < HH; k++) {
            float xk = xr[k];
#pragma unroll
            for (int t = 0; t < 5; t++) {
                float2 w = *reinterpret_cast<const float2*>(sW + k * 80 + c0 + 2 * t);
                acc[2 * t]     = fmaf(xk, w.x, acc[2 * t]);
                acc[2 * t + 1] = fmaf(xk, w.y, acc[2 * t + 1]);
            }
        }
        int row = r0 + q;
        float* dp = (li < 4) ? (g_y2 + (size_t)row * CC + c0)
                             : (g_z2 + (size_t)row * CC + (c0 - 40));
#pragma unroll
        for (int t = 0; t < 5; t++)
            *reinterpret_cast<float2*>(dp + 2 * t) = make_float2(acc[2 * t], acc[2 * t + 1]);
        __syncwarp();
    }
}

// ---------------- K4: conv2 scatter (40 floats/edge) -----------------------
__global__ void k_scatter2() {
    unsigned idx = blockIdx.x * blockDim.x + threadIdx.x;
    if (idx >= (unsigned)EE * 10u) return;
    unsigned e = idx / 10u, c = idx - e * 10u;
    int s = g_src[e];
    int d = g_dst[e];
    float4 v = reinterpret_cast<const float4*>(g_y2 + (size_t)s * CC)[c];
    red_add_v4(g_agg2 + (size_t)d * CC + c * 4, v);
}

// ---------------- K5: out = l2norm(agg2/cnt + bl2 + z2) --------------------
__global__ void k_final(const float* __restrict__ bl2, float* __restrict__ out) {
    int gt = blockIdx.x * blockDim.x + threadIdx.x;
    int n = gt >> 5, lane = gt & 31;
    if (n >= NN) return;
    float invc = 1.f / (float)max(g_cnt[n], 1);
    size_t b = (size_t)n * CC;
    float v0 = g_agg2[b + lane] * invc + bl2[lane] + g_z2[b + lane];
    float v1 = 0.f;
    if (lane < 8)
        v1 = g_agg2[b + 32 + lane] * invc + bl2[32 + lane] + g_z2[b + 32 + lane];
    float s = v0 * v0 + v1 * v1;
#pragma unroll
    for (int o = 16; o > 0; o >>= 1) s += __shfl_xor_sync(0xffffffffu, s, o);
    float inv = 1.f / fmaxf(sqrtf(s), 1e-12f);
    out[b + lane] = v0 * inv;
    if (lane < 8) out[b + 32 + lane] = v1 * inv;
}

// ---------------------------------------------------------------------------
extern "C" void kernel_launch(void* const* d_in, const int* in_sizes, int n_in,
                              void* d_out, int out_size) {
    const float* x      = (const float*)d_in[0];
    const void*  ei     = d_in[1];                 // int32 or int64, detected on-device
    const float* Wl1    = (const float*)d_in[2];
    const float* bl1    = (const float*)d_in[3];
    const float* Wr1    = (const float*)d_in[4];
    const float* Wlin   = (const float*)d_in[5];
    const float* blin   = (const float*)d_in[6];
    const float* Wl2    = (const float*)d_in[7];
    const float* bl2    = (const float*)d_in[8];
    const float* Wr2    = (const float*)d_in[9];
    float* out = (float*)d_out;

    const int smem1 = (3 * FF * HH + 16 * 4 * FF) * (int)sizeof(float);  // 128 KB
    cudaFuncSetAttribute(k_gemm1, cudaFuncAttributeMaxDynamicSharedMemorySize, smem1);

    k_detect<<<1, 256>>>((const unsigned*)ei);
    k_prep<<<3125, 256>>>(ei);               // 800k threads covers zeroing + convert
    k_gemm1<<<148, 512, smem1>>>(x, Wl1, Wr1, Wlin);
    k_scatter1<<<50000, 256>>>();            // E*16 work items exactly
    k_hidden<<<6250, 256>>>(bl1);            // 50000 warps exactly
    k_lin1<<<782, 512>>>(Wlin, blin);
    k_gemm2<<<782, 512>>>(Wl2, Wr2);
    k_scatter2<<<31250, 256>>>();            // E*10 work items exactly
    k_final<<<6250, 256>>>(bl2, out);
}